// round 11
// baseline (speedup 1.0000x reference)
#include <cuda_runtime.h>
#include <cuda_bf16.h>
#include <math.h>

#define NN 50000
#define EE 800000
#define ET (EE + NN)     // edges + self loops
#define HID 128
#define SLOPE 0.2f
#define LN_EPS 1e-5f
#define SCAN_NB 13       // ceil(50000/4096)
#define GEMM_NB 391      // ceil(50000/128)
#define HEADS_NB 782     // ceil(50000/64)

typedef unsigned long long ull;

// ---------------- scratch (device globals; no allocation allowed) ----------
__device__ int   g_deg[NN];          // zero at start of every run (self-restoring)
__device__ int   g_rowptr[NN + 1];
__device__ int   g_cursor[NN];
__device__ int   g_blocksums[64];
__device__ int   g_src[ET + 8];      // +8 pad: unconditional pipelined loads
__device__ float g_xl[NN * HID];
__device__ float g_xr[NN * HID];
__device__ float g_h1[NN * HID];
__device__ float g_h2[NN * HID];

// ---------------- f32x2 packed math helpers --------------------------------
__device__ __forceinline__ ull pk2(float x) {
    ull r; asm("mov.b64 %0, {%1, %1};" : "=l"(r) : "f"(x)); return r;
}
__device__ __forceinline__ ull mk2(float lo, float hi) {
    ull r; asm("mov.b64 %0, {%1, %2};" : "=l"(r) : "f"(lo), "f"(hi)); return r;
}
__device__ __forceinline__ void fma2(ull& d, ull a, ull b) {
    asm("fma.rn.f32x2 %0, %1, %2, %0;" : "+l"(d) : "l"(a), "l"(b));
}
__device__ __forceinline__ ull fma2v(ull a, ull b, ull c) {
    ull r; asm("fma.rn.f32x2 %0, %1, %2, %3;" : "=l"(r) : "l"(a), "l"(b), "l"(c)); return r;
}
__device__ __forceinline__ ull add2v(ull a, ull b) {
    ull r; asm("add.rn.f32x2 %0, %1, %2;" : "=l"(r) : "l"(a), "l"(b)); return r;
}
__device__ __forceinline__ ull mul2v(ull a, ull b) {
    ull r; asm("mul.rn.f32x2 %0, %1, %2;" : "=l"(r) : "l"(a), "l"(b)); return r;
}
__device__ __forceinline__ float2 up2(ull v) {
    float2 f; asm("mov.b64 {%0, %1}, %2;" : "=f"(f.x), "=f"(f.y) : "l"(v)); return f;
}
#define ABS2MASK 0x7FFFFFFF7FFFFFFFull

// ---------------- SGEMM body (R2/R4-proven): Y[M,128] = X[M,K] @ W[K,128] --
template <int K>
__device__ __forceinline__ void gemm_body(const float* __restrict__ X,
                                          const float* __restrict__ W,
                                          float* __restrict__ Y,
                                          int M, int bx) {
    __shared__ float Xs[16][128];   // transposed: Xs[k][row]
    __shared__ float Ws[16][128];

    int tid = threadIdx.x;
    int tx = tid & 15;      // cols tx*8 .. tx*8+7
    int ty = tid >> 4;      // rows ty*8 .. ty*8+7
    int rowBase = bx * 128;

    ull acc[8][4];
#pragma unroll
    for (int r = 0; r < 8; r++)
#pragma unroll
        for (int c = 0; c < 4; c++) acc[r][c] = 0ull;   // bit pattern == {0.f,0.f}

    for (int ks = 0; ks < K; ks += 16) {
        // load X tile transposed
#pragma unroll
        for (int it = 0; it < 2; it++) {
            int f = tid + it * 256;         // 0..511
            int row = f >> 2;               // 0..127
            int k4 = (f & 3) << 2;          // 0,4,8,12
            int gr = rowBase + row;
            float4 v = make_float4(0.f, 0.f, 0.f, 0.f);
            if (gr < M) v = *(const float4*)&X[(size_t)gr * K + ks + k4];
            Xs[k4 + 0][row] = v.x;
            Xs[k4 + 1][row] = v.y;
            Xs[k4 + 2][row] = v.z;
            Xs[k4 + 3][row] = v.w;
        }
        // load W tile
#pragma unroll
        for (int it = 0; it < 2; it++) {
            int f = tid + it * 256;
            int k = f >> 5;                 // 0..15
            int c = (f & 31) << 2;
            *(float4*)&Ws[k][c] = *(const float4*)&W[(size_t)(ks + k) * HID + c];
        }
        __syncthreads();

#pragma unroll
        for (int k = 0; k < 16; k++) {
            float4 xa = *(const float4*)&Xs[k][ty * 8];
            float4 xb = *(const float4*)&Xs[k][ty * 8 + 4];
            ulonglong2 wa = *(const ulonglong2*)&Ws[k][tx * 8];
            ulonglong2 wb = *(const ulonglong2*)&Ws[k][tx * 8 + 4];
            ull xp[8];
            xp[0] = pk2(xa.x); xp[1] = pk2(xa.y); xp[2] = pk2(xa.z); xp[3] = pk2(xa.w);
            xp[4] = pk2(xb.x); xp[5] = pk2(xb.y); xp[6] = pk2(xb.z); xp[7] = pk2(xb.w);
#pragma unroll
            for (int r = 0; r < 8; r++) {
                fma2(acc[r][0], xp[r], wa.x);
                fma2(acc[r][1], xp[r], wa.y);
                fma2(acc[r][2], xp[r], wb.x);
                fma2(acc[r][3], xp[r], wb.y);
            }
        }
        __syncthreads();
    }

#pragma unroll
    for (int r = 0; r < 8; r++) {
        int gr = rowBase + ty * 8 + r;
        if (gr < M) {
            float2 c0 = up2(acc[r][0]), c1 = up2(acc[r][1]);
            float2 c2 = up2(acc[r][2]), c3 = up2(acc[r][3]);
            float4 o0 = {c0.x, c0.y, c1.x, c1.y};
            float4 o1 = {c2.x, c2.y, c3.x, c3.y};
            *(float4*)&Y[(size_t)gr * HID + tx * 8]     = o0;
            *(float4*)&Y[(size_t)gr * HID + tx * 8 + 4] = o1;
        }
    }
}

// ---------------- fused: layer-1 dual GEMM + degree histogram --------------
__global__ void __launch_bounds__(256)
gemm1_hist_kernel(const float* __restrict__ X,
                  const float* __restrict__ WA, const float* __restrict__ WB,
                  float* __restrict__ YA, float* __restrict__ YB,
                  const int* __restrict__ ei, int M) {
    if (blockIdx.x < 2 * GEMM_NB) {
        int sel = blockIdx.x >= GEMM_NB;
        gemm_body<32>(X, sel ? WB : WA, sel ? YB : YA, M,
                      blockIdx.x - sel * GEMM_NB);
    } else {
        int e4 = (blockIdx.x - 2 * GEMM_NB) * 256 + threadIdx.x;
        if (e4 < EE / 4) {
            int4 d = ((const int4*)(ei + EE))[e4];
            atomicAdd(&g_deg[d.x], 1);
            atomicAdd(&g_deg[d.y], 1);
            atomicAdd(&g_deg[d.z], 1);
            atomicAdd(&g_deg[d.w], 1);
        }
    }
}

__global__ void __launch_bounds__(256)
gemm_dual_kernel(const float* __restrict__ X,
                 const float* __restrict__ WA, const float* __restrict__ WB,
                 float* __restrict__ YA, float* __restrict__ YB, int M) {
    gemm_body<128>(X, blockIdx.y ? WB : WA, blockIdx.y ? YB : YA, M, blockIdx.x);
}

// ---------------- CSR scan + scatter (R4-proven multi-block) ----------------
__global__ void scan1_kernel() {
    __shared__ int sh[1024];
    int t = threadIdx.x;
    int base = blockIdx.x * 4096 + t * 4;
    // +1 = implicit self loop per node
    int v0 = (base + 0 < NN) ? g_deg[base + 0] + 1 : 0;
    int v1 = (base + 1 < NN) ? g_deg[base + 1] + 1 : 0;
    int v2 = (base + 2 < NN) ? g_deg[base + 2] + 1 : 0;
    int v3 = (base + 3 < NN) ? g_deg[base + 3] + 1 : 0;
    int p0 = v0, p1 = p0 + v1, p2 = p1 + v2, p3 = p2 + v3;
    sh[t] = p3;
    __syncthreads();
    for (int off = 1; off < 1024; off <<= 1) {
        int add = (t >= off) ? sh[t - off] : 0;
        __syncthreads();
        sh[t] += add;
        __syncthreads();
    }
    int excl = sh[t] - p3;
    if (base + 0 < NN) g_rowptr[base + 0] = excl;
    if (base + 1 < NN) g_rowptr[base + 1] = excl + p0;
    if (base + 2 < NN) g_rowptr[base + 2] = excl + p1;
    if (base + 3 < NN) g_rowptr[base + 3] = excl + p2;
    if (t == 1023) g_blocksums[blockIdx.x] = sh[1023];  // raw block totals
}

__global__ void scan3_kernel() {
    int i = blockIdx.x * blockDim.x + threadIdx.x;
    if (i < NN) {
        int idx = i >> 12;
        int off = 0;
        for (int b = 0; b < idx; b++) off += g_blocksums[b];
        int r = g_rowptr[i] + off;
        g_rowptr[i] = r;
        g_cursor[i] = r;
        g_deg[i] = 0;               // restore for next graph replay
    } else if (i == NN) {
        g_rowptr[NN] = ET;
    }
}

__global__ void scatter_kernel(const int* __restrict__ ei) {
    int i = blockIdx.x * blockDim.x + threadIdx.x;
    if (i >= ET) {
        if (i < ET + 8) g_src[i] = 0;   // zero the pipeline pad (deterministic)
        return;
    }
    int s, d;
    if (i < EE) { s = ei[i]; d = ei[EE + i]; }
    else        { s = i - EE; d = s; }
    int p = atomicAdd(&g_cursor[d], 1);
    g_src[p] = s;
}

// ---------------- GATv2 aggregation core -----------------------------------
// Uniform per-edge src loads (broadcast LDG, L1-resident) -- no SHFL, no
// lane predication, no 32-edge blocking. Flat unroll-4 reload-in-place
// pipeline; loads unconditional (g_src padded by 8, reads past e1 hit other
// nodes' valid ids or the zero pad and are never processed).
// Logits tiny (weights ~0.05) -> exp without max-shift is safe.
// leaky_relu(t) = 0.6t + 0.4|t| for slope 0.2.
__device__ __forceinline__ float4 agg_core(int node, int lane,
                                           const float* __restrict__ xl,
                                           const float* __restrict__ xr,
                                           const float* __restrict__ att) {
    float4 xr4 = *(const float4*)&xr[(size_t)node * HID + lane * 4];
    float4 a4  = *(const float4*)&att[lane * 4];
    const float c6 = 0.5f * (1.f + SLOPE), c4 = 0.5f * (1.f - SLOPE);
    ull xrA = mk2(xr4.x, xr4.y), xrB = mk2(xr4.z, xr4.w);
    ull a06A = mk2(a4.x * c6, a4.y * c6), a06B = mk2(a4.z * c6, a4.w * c6);
    ull a04A = mk2(a4.x * c4, a4.y * c4), a04B = mk2(a4.z * c4, a4.w * c4);

    int e0 = g_rowptr[node], e1 = g_rowptr[node + 1];
    const char* xbase = (const char*)xl + lane * 16;

    ull accA = 0ull, accB = 0ull;      // bit pattern == {0.f,0.f}
    float denom = 0.f;

#define LDE(idx, dA, dB) {                                                    \
        int _s = g_src[(idx)];                                                \
        ulonglong2 _v = *(const ulonglong2*)(xbase + (size_t)_s * (HID * 4)); \
        dA = _v.x; dB = _v.y; }

#define PROCE(cA, cB) {                                                       \
        ull t01 = add2v(cA, xrA), t23 = add2v(cB, xrB);                       \
        ull v2 = mul2v(t01, a06A);                                            \
        v2 = fma2v(t01 & ABS2MASK, a04A, v2);                                 \
        v2 = fma2v(t23, a06B, v2);                                            \
        v2 = fma2v(t23 & ABS2MASK, a04B, v2);                                 \
        float2 vv = up2(v2);                                                  \
        float v = vv.x + vv.y;                                                \
        v += __shfl_xor_sync(0xffffffffu, v, 1);                              \
        v += __shfl_xor_sync(0xffffffffu, v, 2);                              \
        v += __shfl_xor_sync(0xffffffffu, v, 4);                              \
        float e = __expf(v);                                                  \
        denom += e;                                                           \
        ull ep = pk2(e);                                                      \
        fma2(accA, ep, cA);                                                   \
        fma2(accB, ep, cB); }

    ull a0A, a0B, a1A, a1B, a2A, a2B, a3A, a3B;
    LDE(e0 + 0, a0A, a0B);
    LDE(e0 + 1, a1A, a1B);
    LDE(e0 + 2, a2A, a2B);
    LDE(e0 + 3, a3A, a3B);

    int m = e1 - e0;
    int last4 = e0 + (m & ~3);
    int e = e0;
    for (; e < last4; e += 4) {
        PROCE(a0A, a0B); LDE(e + 4, a0A, a0B);
        PROCE(a1A, a1B); LDE(e + 5, a1A, a1B);
        PROCE(a2A, a2B); LDE(e + 6, a2A, a2B);
        PROCE(a3A, a3B); LDE(e + 7, a3A, a3B);
    }
    int rem = e1 - e;              // 0..3, warp-uniform
    if (rem > 0) { PROCE(a0A, a0B); }
    if (rem > 1) { PROCE(a1A, a1B); }
    if (rem > 2) { PROCE(a2A, a2B); }
#undef LDE
#undef PROCE

    float inv = 1.f / denom;
    float2 rA = up2(accA), rB = up2(accB);
    float4 res;
    res.x = rA.x * inv; res.y = rA.y * inv;
    res.z = rB.x * inv; res.w = rB.y * inv;
    return res;
}

__device__ __forceinline__ float4 ln_epi(float4 r, int lane,
                                         const float* __restrict__ bias,
                                         const float* __restrict__ gamma,
                                         const float* __restrict__ beta) {
    float4 b4 = *(const float4*)&bias[lane * 4];
    r.x += b4.x; r.y += b4.y; r.z += b4.z; r.w += b4.w;
    float s1 = r.x + r.y + r.z + r.w;
    float s2 = r.x * r.x + r.y * r.y + r.z * r.z + r.w * r.w;
#pragma unroll
    for (int off = 16; off > 0; off >>= 1) {
        s1 += __shfl_xor_sync(0xffffffffu, s1, off);
        s2 += __shfl_xor_sync(0xffffffffu, s2, off);
    }
    float mean = s1 * (1.f / 128.f);
    float var  = s2 * (1.f / 128.f) - mean * mean;
    float rstd = rsqrtf(var + LN_EPS);
    float4 g4 = *(const float4*)&gamma[lane * 4];
    float4 bb4 = *(const float4*)&beta[lane * 4];
    r.x = (r.x - mean) * rstd * g4.x + bb4.x;
    r.y = (r.y - mean) * rstd * g4.y + bb4.y;
    r.z = (r.z - mean) * rstd * g4.z + bb4.z;
    r.w = (r.w - mean) * rstd * g4.w + bb4.w;
    return r;
}

// ---------------- layer 1: agg + bias + LN + ELU -> h1 ---------------------
__global__ void __launch_bounds__(256)
gat_layer1_kernel(const float* __restrict__ xl, const float* __restrict__ xr,
                  const float* __restrict__ att, const float* __restrict__ bias,
                  const float* __restrict__ gamma, const float* __restrict__ beta,
                  float* __restrict__ out, int Nn) {
    int warp = (blockIdx.x * blockDim.x + threadIdx.x) >> 5;
    if (warp >= Nn) return;
    int lane = threadIdx.x & 31;
    float4 r = agg_core(warp, lane, xl, xr, att);
    r = ln_epi(r, lane, bias, gamma, beta);
    r.x = r.x > 0.f ? r.x : expm1f(r.x);
    r.y = r.y > 0.f ? r.y : expm1f(r.y);
    r.z = r.z > 0.f ? r.z : expm1f(r.z);
    r.w = r.w > 0.f ? r.w : expm1f(r.w);
    *(float4*)&out[(size_t)warp * HID + lane * 4] = r;
}

// ---------------- layer 2: agg + bias + LN + residual + ELU -> h2 ----------
__global__ void __launch_bounds__(256)
gat_layer2_kernel(const float* __restrict__ xl, const float* __restrict__ xr,
                  const float* __restrict__ att, const float* __restrict__ bias,
                  const float* __restrict__ gamma, const float* __restrict__ beta,
                  const float* __restrict__ resid, float* __restrict__ out, int Nn) {
    int warp = (blockIdx.x * blockDim.x + threadIdx.x) >> 5;
    if (warp >= Nn) return;
    int lane = threadIdx.x & 31;
    float4 r = agg_core(warp, lane, xl, xr, att);
    r = ln_epi(r, lane, bias, gamma, beta);
    float4 rs = *(const float4*)&resid[(size_t)warp * HID + lane * 4];
    r.x += rs.x; r.y += rs.y; r.z += rs.z; r.w += rs.w;
    r.x = r.x > 0.f ? r.x : expm1f(r.x);
    r.y = r.y > 0.f ? r.y : expm1f(r.y);
    r.z = r.z > 0.f ? r.z : expm1f(r.z);
    r.w = r.w > 0.f ? r.w : expm1f(r.w);
    *(float4*)&out[(size_t)warp * HID + lane * 4] = r;
}

// ---------------- heads: GEMM-style fused MLP heads ------------------------
__global__ void __launch_bounds__(192)
heads_kernel(const float* __restrict__ h,
             const float* __restrict__ Wp1, const float* __restrict__ bp1,
             const float* __restrict__ Wp2, const float* __restrict__ bp2,
             const float* __restrict__ Wu1, const float* __restrict__ bu1,
             const float* __restrict__ Wu2, const float* __restrict__ bu2,
             float* __restrict__ out, int Nn) {
    __shared__ float hs[64][132];      // padded row-major h tile (33KB)
    __shared__ float wp2s[64 * 6];
    __shared__ float wu2s[32 * 6];

    int tid = threadIdx.x;
    int tx = tid % 12;        // 12 col-groups of 8 (96 = 64 pred + 32 unc)
    int ty = tid / 12;        // 16 row-groups of 4
    int base = blockIdx.x * 64;

    // stage small stage-2 weights
    for (int i = tid; i < 64 * 6; i += 192) wp2s[i] = Wp2[i];
    for (int i = tid; i < 32 * 6; i += 192) wu2s[i] = Wu2[i];

    // stage h tile (coalesced loads, conflict-free float4 STS)
    for (int i = tid; i < 64 * 32; i += 192) {
        int row = i >> 5;
        int c4 = (i & 31) << 2;
        int g = base + row;
        float4 v = make_float4(0.f, 0.f, 0.f, 0.f);
        if (g < Nn) v = *(const float4*)&h[(size_t)g * HID + c4];
        *(float4*)&hs[row][c4] = v;
    }
    __syncthreads();

    // stage 1: hidden layers with FFMA2
    const float* wbase;
    int wstr;
    if (tx < 8) { wbase = Wp1 + tx * 8; wstr = 64; }
    else        { wbase = Wu1 + (tx - 8) * 8; wstr = 32; }
    ull bz[4];
#pragma unroll
    for (int c = 0; c < 4; c++) {
        float blo = (tx < 8) ? bp1[tx * 8 + 2 * c]     : bu1[(tx - 8) * 8 + 2 * c];
        float bhi = (tx < 8) ? bp1[tx * 8 + 2 * c + 1] : bu1[(tx - 8) * 8 + 2 * c + 1];
        bz[c] = mk2(blo, bhi);
    }

    ull acc[4][4];
#pragma unroll
    for (int r = 0; r < 4; r++)
#pragma unroll
        for (int c = 0; c < 4; c++) acc[r][c] = 0ull;

    int r0 = ty * 4;
#pragma unroll 4
    for (int k = 0; k < 128; k++) {
        ull x0 = pk2(hs[r0 + 0][k]);
        ull x1 = pk2(hs[r0 + 1][k]);
        ull x2 = pk2(hs[r0 + 2][k]);
        ull x3 = pk2(hs[r0 + 3][k]);
        ulonglong2 w01 = *(const ulonglong2*)(wbase + (size_t)k * wstr);
        ulonglong2 w23 = *(const ulonglong2*)(wbase + (size_t)k * wstr + 4);
        fma2(acc[0][0], x0, w01.x); fma2(acc[0][1], x0, w01.y);
        fma2(acc[0][2], x0, w23.x); fma2(acc[0][3], x0, w23.y);
        fma2(acc[1][0], x1, w01.x); fma2(acc[1][1], x1, w01.y);
        fma2(acc[1][2], x1, w23.x); fma2(acc[1][3], x1, w23.y);
        fma2(acc[2][0], x2, w01.x); fma2(acc[2][1], x2, w01.y);
        fma2(acc[2][2], x2, w23.x); fma2(acc[2][3], x2, w23.y);
        fma2(acc[3][0], x3, w01.x); fma2(acc[3][1], x3, w01.y);
        fma2(acc[3][2], x3, w23.x); fma2(acc[3][3], x3, w23.y);
    }
    __syncthreads();   // done reading hs; safe to overlay ph/uh

    // overlay ph[64][65], uh[64][33] onto the hs region (padded: conflict-free)
    float* ph = &hs[0][0];
    float* uh = ph + 64 * 65;

#pragma unroll
    for (int r = 0; r < 4; r++) {
        int row = r0 + r;
#pragma unroll
        for (int c = 0; c < 4; c++) {
            float2 v = up2(add2v(acc[r][c], bz[c]));
            v.x = fmaxf(v.x, 0.f);
            v.y = fmaxf(v.y, 0.f);
            if (tx < 8) {
                ph[row * 65 + tx * 8 + 2 * c]     = v.x;
                ph[row * 65 + tx * 8 + 2 * c + 1] = v.y;
            } else {
                uh[row * 33 + (tx - 8) * 8 + 2 * c]     = v.x;
                uh[row * 33 + (tx - 8) * 8 + 2 * c + 1] = v.y;
            }
        }
    }
    __syncthreads();

    // stage 2
    if (tid < 64) {
        int g = base + tid;
        if (g < Nn) {
            ull a0 = mk2(bp2[0], bp2[1]);
            ull a1 = mk2(bp2[2], bp2[3]);
            ull a2 = mk2(bp2[4], bp2[5]);
#pragma unroll 4
            for (int k = 0; k < 64; k++) {
                ull p = pk2(ph[tid * 65 + k]);
                ull w0 = *(const ull*)&wp2s[k * 6];
                ull w1 = *(const ull*)&wp2s[k * 6 + 2];
                ull w2 = *(const ull*)&wp2s[k * 6 + 4];
                fma2(a0, p, w0);
                fma2(a1, p, w1);
                fma2(a2, p, w2);
            }
            float2 o0 = up2(a0), o1 = up2(a1), o2 = up2(a2);
            float* op = &out[(size_t)g * 6];
            op[0] = o0.x; op[1] = o0.y; op[2] = o1.x;
            op[3] = o1.y; op[4] = o2.x; op[5] = o2.y;
        }
    } else if (tid < 128) {
        int n = tid - 64;
        int g = base + n;
        if (g < Nn) {
            ull a0 = mk2(bu2[0], bu2[1]);
            ull a1 = mk2(bu2[2], bu2[3]);
            ull a2 = mk2(bu2[4], bu2[5]);
#pragma unroll 4
            for (int k = 0; k < 32; k++) {
                ull p = pk2(uh[n * 33 + k]);
                ull w0 = *(const ull*)&wu2s[k * 6];
                ull w1 = *(const ull*)&wu2s[k * 6 + 2];
                ull w2 = *(const ull*)&wu2s[k * 6 + 4];
                fma2(a0, p, w0);
                fma2(a1, p, w1);
                fma2(a2, p, w2);
            }
            float q[6];
            float2 o0 = up2(a0), o1 = up2(a1), o2 = up2(a2);
            q[0] = o0.x; q[1] = o0.y; q[2] = o1.x;
            q[3] = o1.y; q[4] = o2.x; q[5] = o2.y;
            float* op = &out[(size_t)Nn * 6 + (size_t)g * 6];
#pragma unroll
            for (int c = 0; c < 6; c++)
                op[c] = fmaxf(q[c], 0.f) + log1pf(__expf(-fabsf(q[c])));
        }
    }
}

// ---------------- launcher -------------------------------------------------
extern "C" void kernel_launch(void* const* d_in, const int* in_sizes, int n_in,
                              void* d_out, int out_size) {
    const float* x     = (const float*)d_in[0];
    const int*   ei    = (const int*)d_in[1];
    const float* Wl1   = (const float*)d_in[2];
    const float* Wr1   = (const float*)d_in[3];
    const float* att1  = (const float*)d_in[4];
    const float* bias1 = (const float*)d_in[5];
    const float* g1    = (const float*)d_in[6];
    const float* b1    = (const float*)d_in[7];
    const float* Wl2   = (const float*)d_in[8];
    const float* Wr2   = (const float*)d_in[9];
    const float* att2  = (const float*)d_in[10];
    const float* bias2 = (const float*)d_in[11];
    const float* g2    = (const float*)d_in[12];
    const float* b2    = (const float*)d_in[13];
    const float* Wp1   = (const float*)d_in[14];
    const float* bp1   = (const float*)d_in[15];
    const float* Wp2   = (const float*)d_in[16];
    const float* bp2   = (const float*)d_in[17];
    const float* Wu1   = (const float*)d_in[18];
    const float* bu1   = (const float*)d_in[19];
    const float* Wu2   = (const float*)d_in[20];
    const float* bu2   = (const float*)d_in[21];
    float* out = (float*)d_out;

    float *xl, *xr, *h1, *h2;
    cudaGetSymbolAddress((void**)&xl, g_xl);
    cudaGetSymbolAddress((void**)&xr, g_xr);
    cudaGetSymbolAddress((void**)&h1, g_h1);
    cudaGetSymbolAddress((void**)&h2, g_h2);

    // fused: layer-1 dual GEMM + degree histogram
    int histBlocks = (EE / 4 + 255) / 256;
    gemm1_hist_kernel<<<2 * GEMM_NB + histBlocks, 256>>>(x, Wl1, Wr1, xl, xr, ei, NN);

    // CSR scan + scatter
    scan1_kernel<<<SCAN_NB, 1024>>>();
    scan3_kernel<<<(NN + 256) / 256, 256>>>();
    scatter_kernel<<<(ET + 255) / 256, 256>>>(ei);

    // layer 1 aggregation
    gat_layer1_kernel<<<(NN + 7) / 8, 256>>>(xl, xr, att1, bias1, g1, b1, h1, NN);

    // layer 2 dual GEMM
    dim3 ggrid(GEMM_NB, 2);
    gemm_dual_kernel<<<ggrid, 256>>>(h1, Wl2, Wr2, xl, xr, NN);

    // layer 2 aggregation -> h2
    gat_layer2_kernel<<<(NN + 7) / 8, 256>>>(
        xl, xr, att2, bias2, g2, b2, h1, h2, NN);

    // MLP heads (GEMM-style)
    heads_kernel<<<HEADS_NB, 192>>>(h2, Wp1, bp1, Wp2, bp2,
                                    Wu1, bu1, Wu2, bu2, out, NN);
}

// round 12
// speedup vs baseline: 1.0260x; 1.0260x over previous
#include <cuda_runtime.h>
#include <cuda_bf16.h>
#include <math.h>

#define NN 50000
#define EE 800000
#define ET (EE + NN)     // edges + self loops
#define HID 128
#define SLOPE 0.2f
#define LN_EPS 1e-5f
#define SCAN_NB 13       // ceil(50000/4096)
#define GEMM_NB 391      // ceil(50000/128)
#define HEADS_NB 782     // ceil(50000/64)

typedef unsigned long long ull;

// ---------------- scratch (device globals; no allocation allowed) ----------
__device__ int   g_deg[NN];          // zero at start of every run (self-restoring)
__device__ int   g_rowptr[NN + 1];
__device__ int   g_cursor[NN];
__device__ int   g_blocksums[64];
__device__ int   g_src[ET + 8];      // +8 pad: unconditional pipelined loads
__device__ float g_xl[NN * HID];
__device__ float g_xr[NN * HID];
__device__ float g_h1[NN * HID];
__device__ float g_h2[NN * HID];

// ---------------- f32x2 packed math helpers --------------------------------
__device__ __forceinline__ ull pk2(float x) {
    ull r; asm("mov.b64 %0, {%1, %1};" : "=l"(r) : "f"(x)); return r;
}
__device__ __forceinline__ ull mk2(float lo, float hi) {
    ull r; asm("mov.b64 %0, {%1, %2};" : "=l"(r) : "f"(lo), "f"(hi)); return r;
}
__device__ __forceinline__ void fma2(ull& d, ull a, ull b) {
    asm("fma.rn.f32x2 %0, %1, %2, %0;" : "+l"(d) : "l"(a), "l"(b));
}
__device__ __forceinline__ ull fma2v(ull a, ull b, ull c) {
    ull r; asm("fma.rn.f32x2 %0, %1, %2, %3;" : "=l"(r) : "l"(a), "l"(b), "l"(c)); return r;
}
__device__ __forceinline__ ull add2v(ull a, ull b) {
    ull r; asm("add.rn.f32x2 %0, %1, %2;" : "=l"(r) : "l"(a), "l"(b)); return r;
}
__device__ __forceinline__ ull mul2v(ull a, ull b) {
    ull r; asm("mul.rn.f32x2 %0, %1, %2;" : "=l"(r) : "l"(a), "l"(b)); return r;
}
__device__ __forceinline__ float2 up2(ull v) {
    float2 f; asm("mov.b64 {%0, %1}, %2;" : "=f"(f.x), "=f"(f.y) : "l"(v)); return f;
}
#define ABS2MASK 0x7FFFFFFF7FFFFFFFull

// ---------------- SGEMM body (R2/R4-proven): Y[M,128] = X[M,K] @ W[K,128] --
template <int K>
__device__ __forceinline__ void gemm_body(const float* __restrict__ X,
                                          const float* __restrict__ W,
                                          float* __restrict__ Y,
                                          int M, int bx) {
    __shared__ float Xs[16][128];   // transposed: Xs[k][row]
    __shared__ float Ws[16][128];

    int tid = threadIdx.x;
    int tx = tid & 15;      // cols tx*8 .. tx*8+7
    int ty = tid >> 4;      // rows ty*8 .. ty*8+7
    int rowBase = bx * 128;

    ull acc[8][4];
#pragma unroll
    for (int r = 0; r < 8; r++)
#pragma unroll
        for (int c = 0; c < 4; c++) acc[r][c] = 0ull;   // bit pattern == {0.f,0.f}

    for (int ks = 0; ks < K; ks += 16) {
        // load X tile transposed
#pragma unroll
        for (int it = 0; it < 2; it++) {
            int f = tid + it * 256;         // 0..511
            int row = f >> 2;               // 0..127
            int k4 = (f & 3) << 2;          // 0,4,8,12
            int gr = rowBase + row;
            float4 v = make_float4(0.f, 0.f, 0.f, 0.f);
            if (gr < M) v = *(const float4*)&X[(size_t)gr * K + ks + k4];
            Xs[k4 + 0][row] = v.x;
            Xs[k4 + 1][row] = v.y;
            Xs[k4 + 2][row] = v.z;
            Xs[k4 + 3][row] = v.w;
        }
        // load W tile
#pragma unroll
        for (int it = 0; it < 2; it++) {
            int f = tid + it * 256;
            int k = f >> 5;                 // 0..15
            int c = (f & 31) << 2;
            *(float4*)&Ws[k][c] = *(const float4*)&W[(size_t)(ks + k) * HID + c];
        }
        __syncthreads();

#pragma unroll
        for (int k = 0; k < 16; k++) {
            float4 xa = *(const float4*)&Xs[k][ty * 8];
            float4 xb = *(const float4*)&Xs[k][ty * 8 + 4];
            ulonglong2 wa = *(const ulonglong2*)&Ws[k][tx * 8];
            ulonglong2 wb = *(const ulonglong2*)&Ws[k][tx * 8 + 4];
            ull xp[8];
            xp[0] = pk2(xa.x); xp[1] = pk2(xa.y); xp[2] = pk2(xa.z); xp[3] = pk2(xa.w);
            xp[4] = pk2(xb.x); xp[5] = pk2(xb.y); xp[6] = pk2(xb.z); xp[7] = pk2(xb.w);
#pragma unroll
            for (int r = 0; r < 8; r++) {
                fma2(acc[r][0], xp[r], wa.x);
                fma2(acc[r][1], xp[r], wa.y);
                fma2(acc[r][2], xp[r], wb.x);
                fma2(acc[r][3], xp[r], wb.y);
            }
        }
        __syncthreads();
    }

#pragma unroll
    for (int r = 0; r < 8; r++) {
        int gr = rowBase + ty * 8 + r;
        if (gr < M) {
            float2 c0 = up2(acc[r][0]), c1 = up2(acc[r][1]);
            float2 c2 = up2(acc[r][2]), c3 = up2(acc[r][3]);
            float4 o0 = {c0.x, c0.y, c1.x, c1.y};
            float4 o1 = {c2.x, c2.y, c3.x, c3.y};
            *(float4*)&Y[(size_t)gr * HID + tx * 8]     = o0;
            *(float4*)&Y[(size_t)gr * HID + tx * 8 + 4] = o1;
        }
    }
}

// ---------------- fused: layer-1 dual GEMM + degree histogram --------------
__global__ void __launch_bounds__(256)
gemm1_hist_kernel(const float* __restrict__ X,
                  const float* __restrict__ WA, const float* __restrict__ WB,
                  float* __restrict__ YA, float* __restrict__ YB,
                  const int* __restrict__ ei, int M) {
    if (blockIdx.x < 2 * GEMM_NB) {
        int sel = blockIdx.x >= GEMM_NB;
        gemm_body<32>(X, sel ? WB : WA, sel ? YB : YA, M,
                      blockIdx.x - sel * GEMM_NB);
    } else {
        int e4 = (blockIdx.x - 2 * GEMM_NB) * 256 + threadIdx.x;
        if (e4 < EE / 4) {
            int4 d = ((const int4*)(ei + EE))[e4];
            atomicAdd(&g_deg[d.x], 1);
            atomicAdd(&g_deg[d.y], 1);
            atomicAdd(&g_deg[d.z], 1);
            atomicAdd(&g_deg[d.w], 1);
        }
    }
}

__global__ void __launch_bounds__(256)
gemm_dual_kernel(const float* __restrict__ X,
                 const float* __restrict__ WA, const float* __restrict__ WB,
                 float* __restrict__ YA, float* __restrict__ YB, int M) {
    gemm_body<128>(X, blockIdx.y ? WB : WA, blockIdx.y ? YB : YA, M, blockIdx.x);
}

// ---------------- CSR scan + scatter (R4-proven multi-block) ----------------
__global__ void scan1_kernel() {
    __shared__ int sh[1024];
    int t = threadIdx.x;
    int base = blockIdx.x * 4096 + t * 4;
    // +1 = implicit self loop per node
    int v0 = (base + 0 < NN) ? g_deg[base + 0] + 1 : 0;
    int v1 = (base + 1 < NN) ? g_deg[base + 1] + 1 : 0;
    int v2 = (base + 2 < NN) ? g_deg[base + 2] + 1 : 0;
    int v3 = (base + 3 < NN) ? g_deg[base + 3] + 1 : 0;
    int p0 = v0, p1 = p0 + v1, p2 = p1 + v2, p3 = p2 + v3;
    sh[t] = p3;
    __syncthreads();
    for (int off = 1; off < 1024; off <<= 1) {
        int add = (t >= off) ? sh[t - off] : 0;
        __syncthreads();
        sh[t] += add;
        __syncthreads();
    }
    int excl = sh[t] - p3;
    if (base + 0 < NN) g_rowptr[base + 0] = excl;
    if (base + 1 < NN) g_rowptr[base + 1] = excl + p0;
    if (base + 2 < NN) g_rowptr[base + 2] = excl + p1;
    if (base + 3 < NN) g_rowptr[base + 3] = excl + p2;
    if (t == 1023) g_blocksums[blockIdx.x] = sh[1023];  // raw block totals
}

__global__ void scan3_kernel() {
    int i = blockIdx.x * blockDim.x + threadIdx.x;
    if (i < NN) {
        int idx = i >> 12;
        int off = 0;
        for (int b = 0; b < idx; b++) off += g_blocksums[b];
        int r = g_rowptr[i] + off;
        g_rowptr[i] = r;
        g_cursor[i] = r;
        g_deg[i] = 0;               // restore for next graph replay
    } else if (i == NN) {
        g_rowptr[NN] = ET;
    }
}

__global__ void scatter_kernel(const int* __restrict__ ei) {
    int i = blockIdx.x * blockDim.x + threadIdx.x;
    if (i >= ET) {
        if (i < ET + 8) g_src[i] = 0;   // zero the pipeline pad (deterministic)
        return;
    }
    int s, d;
    if (i < EE) { s = ei[i]; d = ei[EE + i]; }
    else        { s = i - EE; d = s; }
    int p = atomicAdd(&g_cursor[d], 1);
    g_src[p] = s;
}

// ---------------- GATv2 aggregation core: dual-stream ----------------------
// Each node's edge range is split into two halves processed as interleaved
// INDEPENDENT streams (separate acc/denom, merged at end). The second stream
// gives each warp a latency-hiding chain that does not depend on occupancy.
// Uniform per-edge src loads (broadcast LDG); unconditional loads rely on the
// 8-entry g_src pad. Logits tiny -> exp without max-shift is safe.
// leaky_relu(t) = 0.6t + 0.4|t| for slope 0.2.
__device__ __forceinline__ float4 agg_core(int node, int lane,
                                           const float* __restrict__ xl,
                                           const float* __restrict__ xr,
                                           const float* __restrict__ att) {
    float4 xr4 = *(const float4*)&xr[(size_t)node * HID + lane * 4];
    float4 a4  = *(const float4*)&att[lane * 4];
    const float c6 = 0.5f * (1.f + SLOPE), c4 = 0.5f * (1.f - SLOPE);
    ull xrA = mk2(xr4.x, xr4.y), xrB = mk2(xr4.z, xr4.w);
    ull a06A = mk2(a4.x * c6, a4.y * c6), a06B = mk2(a4.z * c6, a4.w * c6);
    ull a04A = mk2(a4.x * c4, a4.y * c4), a04B = mk2(a4.z * c4, a4.w * c4);

    int e0 = g_rowptr[node], e1 = g_rowptr[node + 1];
    const char* xbase = (const char*)xl + lane * 16;

    ull accA1 = 0ull, accB1 = 0ull, accA2 = 0ull, accB2 = 0ull;
    float den1 = 0.f, den2 = 0.f;

#define LDE(idx, dA, dB) {                                                    \
        int _s = g_src[(idx)];                                                \
        ulonglong2 _v = *(const ulonglong2*)(xbase + (size_t)_s * (HID * 4)); \
        dA = _v.x; dB = _v.y; }

#define PROCE(cA, cB, aA, aB, dn) {                                           \
        ull t01 = add2v(cA, xrA), t23 = add2v(cB, xrB);                       \
        ull v2 = mul2v(t01, a06A);                                            \
        v2 = fma2v(t01 & ABS2MASK, a04A, v2);                                 \
        v2 = fma2v(t23, a06B, v2);                                            \
        v2 = fma2v(t23 & ABS2MASK, a04B, v2);                                 \
        float2 vv = up2(v2);                                                  \
        float v = vv.x + vv.y;                                                \
        v += __shfl_xor_sync(0xffffffffu, v, 1);                              \
        v += __shfl_xor_sync(0xffffffffu, v, 2);                              \
        v += __shfl_xor_sync(0xffffffffu, v, 4);                              \
        float e = __expf(v);                                                  \
        dn += e;                                                              \
        ull ep = pk2(e);                                                      \
        fma2(aA, ep, cA);                                                     \
        fma2(aB, ep, cB); }

    int m = e1 - e0;
    int half = m >> 1;
    int p = e0, q = e0 + half;     // stream1: [e0,e0+half), stream2: [e0+half,e1)

    ull p0A, p0B, p1A, p1B, q0A, q0B, q1A, q1B;
    LDE(p + 0, p0A, p0B);
    LDE(q + 0, q0A, q0B);
    LDE(p + 1, p1A, p1B);
    LDE(q + 1, q1A, q1B);

    int j = 0;
    for (; j + 2 <= half; j += 2) {
        PROCE(p0A, p0B, accA1, accB1, den1); LDE(p + j + 2, p0A, p0B);
        PROCE(q0A, q0B, accA2, accB2, den2); LDE(q + j + 2, q0A, q0B);
        PROCE(p1A, p1B, accA1, accB1, den1); LDE(p + j + 3, p1A, p1B);
        PROCE(q1A, q1B, accA2, accB2, den2); LDE(q + j + 3, q1A, q1B);
    }
    int rem1 = half - j;            // 0 or 1  (warp-uniform)
    int rem2 = (m - half) - j;      // 0..2    (warp-uniform)
    if (rem1 > 0) { PROCE(p0A, p0B, accA1, accB1, den1); }
    if (rem2 > 0) { PROCE(q0A, q0B, accA2, accB2, den2); }
    if (rem2 > 1) { PROCE(q1A, q1B, accA2, accB2, den2); }
#undef LDE
#undef PROCE

    float denom = den1 + den2;
    ull accA = add2v(accA1, accA2);
    ull accB = add2v(accB1, accB2);

    float inv = 1.f / denom;
    float2 rA = up2(accA), rB = up2(accB);
    float4 res;
    res.x = rA.x * inv; res.y = rA.y * inv;
    res.z = rB.x * inv; res.w = rB.y * inv;
    return res;
}

__device__ __forceinline__ float4 ln_epi(float4 r, int lane,
                                         const float* __restrict__ bias,
                                         const float* __restrict__ gamma,
                                         const float* __restrict__ beta) {
    float4 b4 = *(const float4*)&bias[lane * 4];
    r.x += b4.x; r.y += b4.y; r.z += b4.z; r.w += b4.w;
    float s1 = r.x + r.y + r.z + r.w;
    float s2 = r.x * r.x + r.y * r.y + r.z * r.z + r.w * r.w;
#pragma unroll
    for (int off = 16; off > 0; off >>= 1) {
        s1 += __shfl_xor_sync(0xffffffffu, s1, off);
        s2 += __shfl_xor_sync(0xffffffffu, s2, off);
    }
    float mean = s1 * (1.f / 128.f);
    float var  = s2 * (1.f / 128.f) - mean * mean;
    float rstd = rsqrtf(var + LN_EPS);
    float4 g4 = *(const float4*)&gamma[lane * 4];
    float4 bb4 = *(const float4*)&beta[lane * 4];
    r.x = (r.x - mean) * rstd * g4.x + bb4.x;
    r.y = (r.y - mean) * rstd * g4.y + bb4.y;
    r.z = (r.z - mean) * rstd * g4.z + bb4.z;
    r.w = (r.w - mean) * rstd * g4.w + bb4.w;
    return r;
}

// ---------------- layer 1: agg + bias + LN + ELU -> h1 ---------------------
__global__ void __launch_bounds__(128)
gat_layer1_kernel(const float* __restrict__ xl, const float* __restrict__ xr,
                  const float* __restrict__ att, const float* __restrict__ bias,
                  const float* __restrict__ gamma, const float* __restrict__ beta,
                  float* __restrict__ out, int Nn) {
    int warp = (blockIdx.x * blockDim.x + threadIdx.x) >> 5;
    if (warp >= Nn) return;
    int lane = threadIdx.x & 31;
    float4 r = agg_core(warp, lane, xl, xr, att);
    r = ln_epi(r, lane, bias, gamma, beta);
    r.x = r.x > 0.f ? r.x : expm1f(r.x);
    r.y = r.y > 0.f ? r.y : expm1f(r.y);
    r.z = r.z > 0.f ? r.z : expm1f(r.z);
    r.w = r.w > 0.f ? r.w : expm1f(r.w);
    *(float4*)&out[(size_t)warp * HID + lane * 4] = r;
}

// ---------------- layer 2: agg + bias + LN + residual + ELU -> h2 ----------
__global__ void __launch_bounds__(128)
gat_layer2_kernel(const float* __restrict__ xl, const float* __restrict__ xr,
                  const float* __restrict__ att, const float* __restrict__ bias,
                  const float* __restrict__ gamma, const float* __restrict__ beta,
                  const float* __restrict__ resid, float* __restrict__ out, int Nn) {
    int warp = (blockIdx.x * blockDim.x + threadIdx.x) >> 5;
    if (warp >= Nn) return;
    int lane = threadIdx.x & 31;
    float4 r = agg_core(warp, lane, xl, xr, att);
    r = ln_epi(r, lane, bias, gamma, beta);
    float4 rs = *(const float4*)&resid[(size_t)warp * HID + lane * 4];
    r.x += rs.x; r.y += rs.y; r.z += rs.z; r.w += rs.w;
    r.x = r.x > 0.f ? r.x : expm1f(r.x);
    r.y = r.y > 0.f ? r.y : expm1f(r.y);
    r.z = r.z > 0.f ? r.z : expm1f(r.z);
    r.w = r.w > 0.f ? r.w : expm1f(r.w);
    *(float4*)&out[(size_t)warp * HID + lane * 4] = r;
}

// ---------------- heads: GEMM-style fused MLP heads ------------------------
__global__ void __launch_bounds__(192)
heads_kernel(const float* __restrict__ h,
             const float* __restrict__ Wp1, const float* __restrict__ bp1,
             const float* __restrict__ Wp2, const float* __restrict__ bp2,
             const float* __restrict__ Wu1, const float* __restrict__ bu1,
             const float* __restrict__ Wu2, const float* __restrict__ bu2,
             float* __restrict__ out, int Nn) {
    __shared__ float hs[64][132];      // padded row-major h tile (33KB)
    __shared__ float wp2s[64 * 6];
    __shared__ float wu2s[32 * 6];

    int tid = threadIdx.x;
    int tx = tid % 12;        // 12 col-groups of 8 (96 = 64 pred + 32 unc)
    int ty = tid / 12;        // 16 row-groups of 4
    int base = blockIdx.x * 64;

    // stage small stage-2 weights
    for (int i = tid; i < 64 * 6; i += 192) wp2s[i] = Wp2[i];
    for (int i = tid; i < 32 * 6; i += 192) wu2s[i] = Wu2[i];

    // stage h tile (coalesced loads, conflict-free float4 STS)
    for (int i = tid; i < 64 * 32; i += 192) {
        int row = i >> 5;
        int c4 = (i & 31) << 2;
        int g = base + row;
        float4 v = make_float4(0.f, 0.f, 0.f, 0.f);
        if (g < Nn) v = *(const float4*)&h[(size_t)g * HID + c4];
        *(float4*)&hs[row][c4] = v;
    }
    __syncthreads();

    // stage 1: hidden layers with FFMA2
    const float* wbase;
    int wstr;
    if (tx < 8) { wbase = Wp1 + tx * 8; wstr = 64; }
    else        { wbase = Wu1 + (tx - 8) * 8; wstr = 32; }
    ull bz[4];
#pragma unroll
    for (int c = 0; c < 4; c++) {
        float blo = (tx < 8) ? bp1[tx * 8 + 2 * c]     : bu1[(tx - 8) * 8 + 2 * c];
        float bhi = (tx < 8) ? bp1[tx * 8 + 2 * c + 1] : bu1[(tx - 8) * 8 + 2 * c + 1];
        bz[c] = mk2(blo, bhi);
    }

    ull acc[4][4];
#pragma unroll
    for (int r = 0; r < 4; r++)
#pragma unroll
        for (int c = 0; c < 4; c++) acc[r][c] = 0ull;

    int r0 = ty * 4;
#pragma unroll 4
    for (int k = 0; k < 128; k++) {
        ull x0 = pk2(hs[r0 + 0][k]);
        ull x1 = pk2(hs[r0 + 1][k]);
        ull x2 = pk2(hs[r0 + 2][k]);
        ull x3 = pk2(hs[r0 + 3][k]);
        ulonglong2 w01 = *(const ulonglong2*)(wbase + (size_t)k * wstr);
        ulonglong2 w23 = *(const ulonglong2*)(wbase + (size_t)k * wstr + 4);
        fma2(acc[0][0], x0, w01.x); fma2(acc[0][1], x0, w01.y);
        fma2(acc[0][2], x0, w23.x); fma2(acc[0][3], x0, w23.y);
        fma2(acc[1][0], x1, w01.x); fma2(acc[1][1], x1, w01.y);
        fma2(acc[1][2], x1, w23.x); fma2(acc[1][3], x1, w23.y);
        fma2(acc[2][0], x2, w01.x); fma2(acc[2][1], x2, w01.y);
        fma2(acc[2][2], x2, w23.x); fma2(acc[2][3], x2, w23.y);
        fma2(acc[3][0], x3, w01.x); fma2(acc[3][1], x3, w01.y);
        fma2(acc[3][2], x3, w23.x); fma2(acc[3][3], x3, w23.y);
    }
    __syncthreads();   // done reading hs; safe to overlay ph/uh

    // overlay ph[64][65], uh[64][33] onto the hs region (padded: conflict-free)
    float* ph = &hs[0][0];
    float* uh = ph + 64 * 65;

#pragma unroll
    for (int r = 0; r < 4; r++) {
        int row = r0 + r;
#pragma unroll
        for (int c = 0; c < 4; c++) {
            float2 v = up2(add2v(acc[r][c], bz[c]));
            v.x = fmaxf(v.x, 0.f);
            v.y = fmaxf(v.y, 0.f);
            if (tx < 8) {
                ph[row * 65 + tx * 8 + 2 * c]     = v.x;
                ph[row * 65 + tx * 8 + 2 * c + 1] = v.y;
            } else {
                uh[row * 33 + (tx - 8) * 8 + 2 * c]     = v.x;
                uh[row * 33 + (tx - 8) * 8 + 2 * c + 1] = v.y;
            }
        }
    }
    __syncthreads();

    // stage 2
    if (tid < 64) {
        int g = base + tid;
        if (g < Nn) {
            ull a0 = mk2(bp2[0], bp2[1]);
            ull a1 = mk2(bp2[2], bp2[3]);
            ull a2 = mk2(bp2[4], bp2[5]);
#pragma unroll 4
            for (int k = 0; k < 64; k++) {
                ull p = pk2(ph[tid * 65 + k]);
                ull w0 = *(const ull*)&wp2s[k * 6];
                ull w1 = *(const ull*)&wp2s[k * 6 + 2];
                ull w2 = *(const ull*)&wp2s[k * 6 + 4];
                fma2(a0, p, w0);
                fma2(a1, p, w1);
                fma2(a2, p, w2);
            }
            float2 o0 = up2(a0), o1 = up2(a1), o2 = up2(a2);
            float* op = &out[(size_t)g * 6];
            op[0] = o0.x; op[1] = o0.y; op[2] = o1.x;
            op[3] = o1.y; op[4] = o2.x; op[5] = o2.y;
        }
    } else if (tid < 128) {
        int n = tid - 64;
        int g = base + n;
        if (g < Nn) {
            ull a0 = mk2(bu2[0], bu2[1]);
            ull a1 = mk2(bu2[2], bu2[3]);
            ull a2 = mk2(bu2[4], bu2[5]);
#pragma unroll 4
            for (int k = 0; k < 32; k++) {
                ull p = pk2(uh[n * 33 + k]);
                ull w0 = *(const ull*)&wu2s[k * 6];
                ull w1 = *(const ull*)&wu2s[k * 6 + 2];
                ull w2 = *(const ull*)&wu2s[k * 6 + 4];
                fma2(a0, p, w0);
                fma2(a1, p, w1);
                fma2(a2, p, w2);
            }
            float q[6];
            float2 o0 = up2(a0), o1 = up2(a1), o2 = up2(a2);
            q[0] = o0.x; q[1] = o0.y; q[2] = o1.x;
            q[3] = o1.y; q[4] = o2.x; q[5] = o2.y;
            float* op = &out[(size_t)Nn * 6 + (size_t)g * 6];
#pragma unroll
            for (int c = 0; c < 6; c++)
                op[c] = fmaxf(q[c], 0.f) + log1pf(__expf(-fabsf(q[c])));
        }
    }
}

// ---------------- launcher -------------------------------------------------
extern "C" void kernel_launch(void* const* d_in, const int* in_sizes, int n_in,
                              void* d_out, int out_size) {
    const float* x     = (const float*)d_in[0];
    const int*   ei    = (const int*)d_in[1];
    const float* Wl1   = (const float*)d_in[2];
    const float* Wr1   = (const float*)d_in[3];
    const float* att1  = (const float*)d_in[4];
    const float* bias1 = (const float*)d_in[5];
    const float* g1    = (const float*)d_in[6];
    const float* b1    = (const float*)d_in[7];
    const float* Wl2   = (const float*)d_in[8];
    const float* Wr2   = (const float*)d_in[9];
    const float* att2  = (const float*)d_in[10];
    const float* bias2 = (const float*)d_in[11];
    const float* g2    = (const float*)d_in[12];
    const float* b2    = (const float*)d_in[13];
    const float* Wp1   = (const float*)d_in[14];
    const float* bp1   = (const float*)d_in[15];
    const float* Wp2   = (const float*)d_in[16];
    const float* bp2   = (const float*)d_in[17];
    const float* Wu1   = (const float*)d_in[18];
    const float* bu1   = (const float*)d_in[19];
    const float* Wu2   = (const float*)d_in[20];
    const float* bu2   = (const float*)d_in[21];
    float* out = (float*)d_out;

    float *xl, *xr, *h1, *h2;
    cudaGetSymbolAddress((void**)&xl, g_xl);
    cudaGetSymbolAddress((void**)&xr, g_xr);
    cudaGetSymbolAddress((void**)&h1, g_h1);
    cudaGetSymbolAddress((void**)&h2, g_h2);

    // fused: layer-1 dual GEMM + degree histogram
    int histBlocks = (EE / 4 + 255) / 256;
    gemm1_hist_kernel<<<2 * GEMM_NB + histBlocks, 256>>>(x, Wl1, Wr1, xl, xr, ei, NN);

    // CSR scan + scatter
    scan1_kernel<<<SCAN_NB, 1024>>>();
    scan3_kernel<<<(NN + 256) / 256, 256>>>();
    scatter_kernel<<<(ET + 255) / 256, 256>>>(ei);

    // layer 1 aggregation (4 warps/block for reg-pressure headroom)
    gat_layer1_kernel<<<(NN + 3) / 4, 128>>>(xl, xr, att1, bias1, g1, b1, h1, NN);

    // layer 2 dual GEMM
    dim3 ggrid(GEMM_NB, 2);
    gemm_dual_kernel<<<ggrid, 256>>>(h1, Wl2, Wr2, xl, xr, NN);

    // layer 2 aggregation -> h2
    gat_layer2_kernel<<<(NN + 3) / 4, 128>>>(
        xl, xr, att2, bias2, g2, b2, h1, h2, NN);

    // MLP heads (GEMM-style)
    heads_kernel<<<HEADS_NB, 192>>>(h2, Wp1, bp1, Wp2, bp2,
                                    Wu1, bu1, Wu2, bu2, out, NN);
}